// round 2
// baseline (speedup 1.0000x reference)
#include <cuda_runtime.h>
#include <cuda_bf16.h>
#include <math.h>

// FlashChatglmAttention: B=4 S=1024 HID=4096 NH=32 HS=128 ROT=64
// Stages: QKV sgemm -> rotary+kv-scatter -> causal flash attention -> dense sgemm
// Round 1: fp32 SIMT baseline. Outputs: [out (T*HID) | kv_k (T*HID) | kv_v (T*HID)]

#define TT    4096
#define HIDN  4096
#define NHEAD 32
#define HSZ   128
#define SEQ   1024
#define BATCH 4

// Scratch (allocation-free per harness rules)
__device__ float g_qkv [(size_t)TT * 3 * HIDN];  // raw qkv projection
__device__ float g_q   [(size_t)TT * HIDN];      // rotated q, (T, NH, HS)
__device__ float g_attn[(size_t)TT * HIDN];      // attention output, (T, NH*HS)

// ---------------------------------------------------------------------------
// SGEMM: C[M,N] = A[M,K] @ B[K,N] (+bias). Row-major. M,N,K multiples of 128/16.
// 128x128 block tile, 16 k-tile, 256 threads, 8x8 per thread, double-buffered.
// ---------------------------------------------------------------------------
__global__ __launch_bounds__(256, 2) void sgemm128(
    const float* __restrict__ A, const float* __restrict__ B,
    const float* __restrict__ bias, float* __restrict__ C,
    int M, int N, int K)
{
    __shared__ float As[2][16][132];   // transposed A tile [k][m], pad 4 (float4-aligned)
    __shared__ float Bs[2][16][128];   // B tile [k][n]

    const int tid = threadIdx.x;
    const int tx  = tid & 15;
    const int ty  = tid >> 4;
    const int bm  = blockIdx.y << 7;
    const int bn  = blockIdx.x << 7;

    const int am  = tid >> 2;   // A tile: row within [0,64), +64 for second half
    const int akq = tid & 3;    // which float4 along k
    const int bk  = tid >> 5;   // B tile: k row within [0,8), +8 for second half
    const int bnq = tid & 31;   // which float4 along n

    float acc[8][8];
    #pragma unroll
    for (int i = 0; i < 8; i++)
        #pragma unroll
        for (int j = 0; j < 8; j++) acc[i][j] = 0.f;

    float4 a0r, a1r, b0r, b1r;

    // prologue: load k-tile 0
    {
        const float* Ap = A + (size_t)(bm + am) * K + akq * 4;
        a0r = *(const float4*)Ap;
        a1r = *(const float4*)(Ap + (size_t)64 * K);
        const float* Bp = B + (size_t)bk * N + bn + bnq * 4;
        b0r = *(const float4*)Bp;
        b1r = *(const float4*)(Bp + (size_t)8 * N);
        As[0][akq*4+0][am] = a0r.x; As[0][akq*4+1][am] = a0r.y;
        As[0][akq*4+2][am] = a0r.z; As[0][akq*4+3][am] = a0r.w;
        As[0][akq*4+0][am+64] = a1r.x; As[0][akq*4+1][am+64] = a1r.y;
        As[0][akq*4+2][am+64] = a1r.z; As[0][akq*4+3][am+64] = a1r.w;
        *(float4*)&Bs[0][bk  ][bnq*4] = b0r;
        *(float4*)&Bs[0][bk+8][bnq*4] = b1r;
    }
    __syncthreads();

    const int nk = K >> 4;
    for (int kt = 0; kt < nk; kt++) {
        const int cur = kt & 1;
        if (kt + 1 < nk) {
            const size_t k0 = (size_t)(kt + 1) << 4;
            const float* Ap = A + (size_t)(bm + am) * K + k0 + akq * 4;
            a0r = *(const float4*)Ap;
            a1r = *(const float4*)(Ap + (size_t)64 * K);
            const float* Bp = B + (k0 + bk) * (size_t)N + bn + bnq * 4;
            b0r = *(const float4*)Bp;
            b1r = *(const float4*)(Bp + (size_t)8 * N);
        }
        #pragma unroll
        for (int k = 0; k < 16; k++) {
            float4 qa  = *(const float4*)&As[cur][k][ty*8];
            float4 qb  = *(const float4*)&As[cur][k][ty*8+4];
            float4 pb0 = *(const float4*)&Bs[cur][k][tx*8];
            float4 pb1 = *(const float4*)&Bs[cur][k][tx*8+4];
            float ar[8] = {qa.x,qa.y,qa.z,qa.w,qb.x,qb.y,qb.z,qb.w};
            float br[8] = {pb0.x,pb0.y,pb0.z,pb0.w,pb1.x,pb1.y,pb1.z,pb1.w};
            #pragma unroll
            for (int i = 0; i < 8; i++)
                #pragma unroll
                for (int j = 0; j < 8; j++)
                    acc[i][j] = fmaf(ar[i], br[j], acc[i][j]);
        }
        if (kt + 1 < nk) {
            const int nxt = cur ^ 1;
            As[nxt][akq*4+0][am] = a0r.x; As[nxt][akq*4+1][am] = a0r.y;
            As[nxt][akq*4+2][am] = a0r.z; As[nxt][akq*4+3][am] = a0r.w;
            As[nxt][akq*4+0][am+64] = a1r.x; As[nxt][akq*4+1][am+64] = a1r.y;
            As[nxt][akq*4+2][am+64] = a1r.z; As[nxt][akq*4+3][am+64] = a1r.w;
            *(float4*)&Bs[nxt][bk  ][bnq*4] = b0r;
            *(float4*)&Bs[nxt][bk+8][bnq*4] = b1r;
            __syncthreads();
        }
    }

    #pragma unroll
    for (int i = 0; i < 8; i++) {
        float* Cp = C + (size_t)(bm + ty*8 + i) * N + bn + tx*8;
        float o[8];
        #pragma unroll
        for (int j = 0; j < 8; j++) o[j] = acc[i][j];
        if (bias) {
            const float* bp = bias + bn + tx*8;
            #pragma unroll
            for (int j = 0; j < 8; j++) o[j] += bp[j];
        }
        *(float4*)Cp       = make_float4(o[0], o[1], o[2], o[3]);
        *(float4*)(Cp + 4) = make_float4(o[4], o[5], o[6], o[7]);
    }
}

// ---------------------------------------------------------------------------
// Rotary (first 64 dims per head) on q,k; scatter k,v into kv cache layout.
// One thread per (t, h, d). qkv layout: [t][12288] = q|k|v each (NH,HS).
// ---------------------------------------------------------------------------
__global__ __launch_bounds__(256) void rotary_scatter(
    const float* __restrict__ qkv, const float* __restrict__ cosb,
    const float* __restrict__ sinb, const int* __restrict__ slots,
    float* __restrict__ qout, float* __restrict__ kout, float* __restrict__ vout)
{
    const int idx = blockIdx.x * 256 + threadIdx.x;   // [0, TT*HIDN)
    const int t  = idx >> 12;
    const int hd = idx & 4095;
    const int d  = hd & 127;
    const float* base = qkv + (size_t)t * 12288;
    float qv = base[hd];
    float kv = base[4096 + hd];
    float vv = base[8192 + hd];
    if (d < 64) {
        const int half = d & 31;
        const float c = cosb[(t << 5) + half];
        const float s = sinb[(t << 5) + half];
        if (d < 32) {
            qv = qv * c - base[hd + 32] * s;
            kv = kv * c - base[4096 + hd + 32] * s;
        } else {
            qv = qv * c + base[hd - 32] * s;
            kv = kv * c + base[4096 + hd - 32] * s;
        }
    }
    qout[idx] = qv;
    const size_t ko = ((size_t)slots[t] << 12) + hd;
    kout[ko] = kv;
    vout[ko] = vv;
}

// ---------------------------------------------------------------------------
// Causal flash attention, fp32. Br=Bc=64, 256 threads.
// grid = (SEQ/64, NH, B). Q pre-scaled by 1/sqrt(HS).
// ---------------------------------------------------------------------------
__global__ __launch_bounds__(256) void attn_kernel(
    const float* __restrict__ Q, const float* __restrict__ Kc,
    const float* __restrict__ Vc, float* __restrict__ O)
{
    extern __shared__ float sm[];
    float* Qs   = sm;                   // [64][128]
    float* Ks   = Qs + 64 * 128;        // [64][129]  (pad 1: conflict-light col reads)
    float* Vs   = Ks + 64 * 129;        // [64][132]  (pad 4: float4-aligned)
    float* Ps   = Vs + 64 * 132;        // [64][66]
    float* mrow = Ps + 64 * 66;         // [64]
    float* lrow = mrow + 64;            // [64]
    float* arow = lrow + 64;            // [64]

    const int qi = blockIdx.x, h = blockIdx.y, b = blockIdx.z;
    const int tid = threadIdx.x;
    const int tx = tid & 15, ty = tid >> 4;
    const int q0 = qi << 6;
    const float scale = 0.08838834764831845f;   // 1/sqrt(128)

    #pragma unroll
    for (int i = 0; i < 8; i++) {
        const int f = tid + (i << 8);
        const int r = f >> 5, dq = f & 31;
        const float4 v = *(const float4*)&Q[(size_t)(b*SEQ + q0 + r) * HIDN + h*HSZ + dq*4];
        *(float4*)&Qs[r*128 + dq*4] =
            make_float4(v.x*scale, v.y*scale, v.z*scale, v.w*scale);
    }
    if (tid < 64) { mrow[tid] = -1e30f; lrow[tid] = 0.f; }
    float o[4][8];
    #pragma unroll
    for (int i = 0; i < 4; i++)
        #pragma unroll
        for (int j = 0; j < 8; j++) o[i][j] = 0.f;
    __syncthreads();

    for (int kt = 0; kt <= qi; kt++) {
        #pragma unroll
        for (int i = 0; i < 8; i++) {
            const int f = tid + (i << 8);
            const int r = f >> 5, dq = f & 31;
            const size_t g = (size_t)(b*SEQ + (kt<<6) + r) * HIDN + h*HSZ + dq*4;
            const float4 kv = *(const float4*)&Kc[g];
            Ks[r*129 + dq*4 + 0] = kv.x; Ks[r*129 + dq*4 + 1] = kv.y;
            Ks[r*129 + dq*4 + 2] = kv.z; Ks[r*129 + dq*4 + 3] = kv.w;
            *(float4*)&Vs[r*132 + dq*4] = *(const float4*)&Vc[g];
        }
        __syncthreads();

        // S = Q @ K^T (4x4 per thread)
        float s[4][4];
        #pragma unroll
        for (int i = 0; i < 4; i++)
            #pragma unroll
            for (int j = 0; j < 4; j++) s[i][j] = 0.f;
        #pragma unroll 4
        for (int d = 0; d < 128; d++) {
            float qr[4], kr[4];
            #pragma unroll
            for (int i = 0; i < 4; i++) qr[i] = Qs[(ty*4 + i)*128 + d];
            #pragma unroll
            for (int j = 0; j < 4; j++) kr[j] = Ks[(tx*4 + j)*129 + d];
            #pragma unroll
            for (int i = 0; i < 4; i++)
                #pragma unroll
                for (int j = 0; j < 4; j++)
                    s[i][j] = fmaf(qr[i], kr[j], s[i][j]);
        }
        // causal mask + stage to smem
        #pragma unroll
        for (int i = 0; i < 4; i++) {
            const int qr_ = q0 + ty*4 + i;
            #pragma unroll
            for (int j = 0; j < 4; j++) {
                const int kc = (kt << 6) + tx*4 + j;
                Ps[(ty*4 + i)*66 + tx*4 + j] = (kc <= qr_) ? s[i][j] : -1e30f;
            }
        }
        __syncthreads();

        // online softmax, one thread per row
        if (tid < 64) {
            float mold = mrow[tid];
            float mnew = mold;
            float* pr = &Ps[tid * 66];
            #pragma unroll 8
            for (int c = 0; c < 64; c++) mnew = fmaxf(mnew, pr[c]);
            const float alpha = __expf(mold - mnew);
            float lsum = 0.f;
            #pragma unroll 8
            for (int c = 0; c < 64; c++) {
                const float p = __expf(pr[c] - mnew);
                pr[c] = p; lsum += p;
            }
            lrow[tid] = lrow[tid] * alpha + lsum;
            mrow[tid] = mnew;
            arow[tid] = alpha;
        }
        __syncthreads();

        // rescale accumulator, then O += P @ V
        float al[4];
        #pragma unroll
        for (int i = 0; i < 4; i++) al[i] = arow[ty*4 + i];
        #pragma unroll
        for (int i = 0; i < 4; i++)
            #pragma unroll
            for (int j = 0; j < 8; j++) o[i][j] *= al[i];
        #pragma unroll 2
        for (int k = 0; k < 64; k++) {
            float p[4];
            #pragma unroll
            for (int i = 0; i < 4; i++) p[i] = Ps[(ty*4 + i)*66 + k];
            const float4 v0 = *(const float4*)&Vs[k*132 + tx*8];
            const float4 v1 = *(const float4*)&Vs[k*132 + tx*8 + 4];
            const float vv[8] = {v0.x,v0.y,v0.z,v0.w,v1.x,v1.y,v1.z,v1.w};
            #pragma unroll
            for (int i = 0; i < 4; i++)
                #pragma unroll
                for (int j = 0; j < 8; j++)
                    o[i][j] = fmaf(p[i], vv[j], o[i][j]);
        }
        __syncthreads();
    }

    #pragma unroll
    for (int i = 0; i < 4; i++) {
        const float inv = 1.f / lrow[ty*4 + i];
        float* dst = &O[(size_t)(b*SEQ + q0 + ty*4 + i) * HIDN + h*HSZ + tx*8];
        *(float4*)dst       = make_float4(o[i][0]*inv, o[i][1]*inv, o[i][2]*inv, o[i][3]*inv);
        *(float4*)(dst + 4) = make_float4(o[i][4]*inv, o[i][5]*inv, o[i][6]*inv, o[i][7]*inv);
    }
}

// ---------------------------------------------------------------------------
extern "C" void kernel_launch(void* const* d_in, const int* in_sizes, int n_in,
                              void* d_out, int out_size)
{
    (void)in_sizes; (void)n_in; (void)out_size;
    const float* hs     = (const float*)d_in[0];
    const float* cosb   = (const float*)d_in[1];
    const float* sinb   = (const float*)d_in[2];
    const float* wqkv   = (const float*)d_in[3];
    const float* bqkv   = (const float*)d_in[4];
    const float* wdense = (const float*)d_in[5];
    const int*   slots  = (const int*)d_in[8];

    float* out = (float*)d_out;                     // [TT*HIDN]
    float* kvk = out + (size_t)TT * HIDN;           // [TT*HIDN]
    float* kvv = kvk + (size_t)TT * HIDN;           // [TT*HIDN]

    float *qkv_p, *q_p, *attn_p;
    cudaGetSymbolAddress((void**)&qkv_p,  g_qkv);
    cudaGetSymbolAddress((void**)&q_p,    g_q);
    cudaGetSymbolAddress((void**)&attn_p, g_attn);

    // 1. QKV projection (+bias)
    sgemm128<<<dim3(3*HIDN/128, TT/128), 256>>>(hs, wqkv, bqkv, qkv_p, TT, 3*HIDN, HIDN);

    // 2. rotary + kv-cache scatter (kv outputs written directly)
    rotary_scatter<<<(TT*HIDN)/256, 256>>>(qkv_p, cosb, sinb, slots, q_p, kvk, kvv);

    // 3. causal flash attention
    const size_t smem = (size_t)(64*128 + 64*129 + 64*132 + 64*66 + 192) * sizeof(float);
    cudaFuncSetAttribute(attn_kernel, cudaFuncAttributeMaxDynamicSharedMemorySize, (int)smem);
    attn_kernel<<<dim3(SEQ/64, NHEAD, BATCH), 256, smem>>>(q_p, kvk, kvv, attn_p);

    // 4. dense projection
    sgemm128<<<dim3(HIDN/128, TT/128), 256>>>(attn_p, wdense, nullptr, out, TT, HIDN, HIDN);
}

// round 4
// speedup vs baseline: 1.6152x; 1.6152x over previous
#include <cuda_runtime.h>
#include <cuda_bf16.h>
#include <math.h>
#include <stdint.h>

// FlashChatglmAttention: B=4 S=1024 HID=4096 NH=32 HS=128 ROT=64
// R4: GEMMs on mma.sync bf16 (hi/lo split x3 for fp32-class accuracy).
// NOTE: harness compiles for compute_103 (no 'a') -> tcgen05 unavailable;
// mma.sync/ldmatrix/cp.async are baseline PTX and hit the tensor pipe (HMMA).

#define TT    4096
#define HIDN  4096
#define NHEAD 32
#define HSZ   128
#define SEQ   1024
#define BATCH 4
#define GK    4096
#define LDP   8192      // packed row stride (hi|lo)

// ---------------- scratch (allocation-free) ----------------
__device__ float g_qkv [(size_t)TT * 3 * HIDN];
__device__ float g_q   [(size_t)TT * HIDN];
__device__ float g_attn[(size_t)TT * HIDN];
__device__ __nv_bfloat16 g_pa [(size_t)TT * LDP];
__device__ __nv_bfloat16 g_pbq[(size_t)3 * HIDN * LDP];
__device__ __nv_bfloat16 g_pbd[(size_t)HIDN * LDP];

// ---------------- PTX helpers (baseline ISA only) ----------------
__device__ __forceinline__ uint32_t smem_u32(const void* p) {
    uint32_t a;
    asm("{ .reg .u64 t; cvta.to.shared.u64 t, %1; cvt.u32.u64 %0, t; }" : "=r"(a) : "l"(p));
    return a;
}
__device__ __forceinline__ void cp_async16(uint32_t saddr, const void* gaddr) {
    asm volatile("cp.async.cg.shared.global [%0], [%1], 16;" :: "r"(saddr), "l"(gaddr));
}
__device__ __forceinline__ void cp_commit() { asm volatile("cp.async.commit_group;"); }
template<int N> __device__ __forceinline__ void cp_wait() {
    asm volatile("cp.async.wait_group %0;" :: "n"(N));
}
__device__ __forceinline__ void ldsm4(uint32_t* r, uint32_t addr) {
    asm volatile("ldmatrix.sync.aligned.m8n8.x4.shared.b16 {%0,%1,%2,%3}, [%4];"
                 : "=r"(r[0]), "=r"(r[1]), "=r"(r[2]), "=r"(r[3]) : "r"(addr));
}
__device__ __forceinline__ void mma16816(float* c, const uint32_t* a, const uint32_t* b) {
    asm volatile("mma.sync.aligned.m16n8k16.row.col.f32.bf16.bf16.f32 "
                 "{%0,%1,%2,%3}, {%4,%5,%6,%7}, {%8,%9}, {%0,%1,%2,%3};"
                 : "+f"(c[0]), "+f"(c[1]), "+f"(c[2]), "+f"(c[3])
                 : "r"(a[0]), "r"(a[1]), "r"(a[2]), "r"(a[3]), "r"(b[0]), "r"(b[1]));
}

// ---------------------------------------------------------------------------
// Pack kernels: fp32 -> bf16 hi | lo (residual).
// ---------------------------------------------------------------------------
__global__ __launch_bounds__(256) void pack_a(const float* __restrict__ X,
                                              __nv_bfloat16* __restrict__ Y) {
    const int idx = blockIdx.x * 256 + threadIdx.x;
    const int m = idx >> 12, k = idx & 4095;
    const float x = X[idx];
    const __nv_bfloat16 h = __float2bfloat16(x);
    const float r = x - __bfloat162float(h);
    Y[(size_t)m * LDP + k]      = h;
    Y[(size_t)m * LDP + GK + k] = __float2bfloat16(r);
}

// transpose pack: W[K][N] -> Y[N][hi(K)|lo(K)]
__global__ __launch_bounds__(1024) void pack_bt(const float* __restrict__ W,
                                                __nv_bfloat16* __restrict__ Y, int N) {
    __shared__ float sm[32][33];
    const int n0 = blockIdx.x << 5, k0 = blockIdx.y << 5;
    sm[threadIdx.y][threadIdx.x] = W[(size_t)(k0 + threadIdx.y) * N + n0 + threadIdx.x];
    __syncthreads();
    const float x = sm[threadIdx.x][threadIdx.y];       // W[k0+tx][n0+ty]
    const int n = n0 + threadIdx.y, k = k0 + threadIdx.x;
    const __nv_bfloat16 h = __float2bfloat16(x);
    const float r = x - __bfloat162float(h);
    Y[(size_t)n * LDP + k]      = h;
    Y[(size_t)n * LDP + GK + k] = __float2bfloat16(r);
}

// ---------------------------------------------------------------------------
// bf16 mma.sync GEMM: C[M][N] = sum of 3 split passes of Ap @ Bp^T (+bias).
// A packed [M][2*GK], Bt packed [N][2*GK]. 128x128 CTA tile, BK=32,
// 8 warps (4x2), 32x64 warp tile, cp.async double buffer.
// ---------------------------------------------------------------------------
#define BK 32
#define SMS 40          // smem row stride in bf16 (80 bytes)
#define BUFB (128 * SMS * 2)  // bytes per buffer

__global__ __launch_bounds__(256) void tgemm(
    const __nv_bfloat16* __restrict__ A, const __nv_bfloat16* __restrict__ Bt,
    const float* __restrict__ bias, float* __restrict__ C, int M, int N)
{
    __shared__ __align__(16) __nv_bfloat16 As[2][128 * SMS];
    __shared__ __align__(16) __nv_bfloat16 Bs[2][128 * SMS];

    const int tid = threadIdx.x;
    const int wid = tid >> 5, lane = tid & 31;
    const int warp_m = wid >> 1, warp_n = wid & 1;
    const uint32_t sA = smem_u32(As), sB = smem_u32(Bs);

    const int m0 = blockIdx.y << 7, n0 = blockIdx.x << 7;
    const __nv_bfloat16* Ap = A + (size_t)m0 * LDP;
    const __nv_bfloat16* Bp = Bt + (size_t)n0 * LDP;

    // per-lane ldmatrix address components
    const int arow = lane & 15;                       // A: row within m16 tile
    const int akb  = (lane >> 4) * 16;                // A: k-byte offset (8 bf16)
    const int brow = ((lane >> 4) << 3) + (lane & 7); // B: row within n16 tile
    const int bkb  = ((lane >> 3) & 1) * 16;          // B: k-byte offset

    float c[2][8][4];
    #pragma unroll
    for (int i = 0; i < 2; i++)
        #pragma unroll
        for (int j = 0; j < 8; j++)
            #pragma unroll
            for (int v = 0; v < 4; v++) c[i][j][v] = 0.f;

    // split passes: (Ah,Bh), (Ah,Bl), (Al,Bh)
    const int kaoff[3] = {0, 0, GK};
    const int kboff[3] = {0, GK, 0};
    const int NT = 3 * (GK / BK);   // 384 k-tiles

    auto issue = [&](int buf, int t) {
        const int pass = t >> 7, kt = t & 127;
        const int ao = kaoff[pass] + kt * BK;
        const int bo = kboff[pass] + kt * BK;
        #pragma unroll
        for (int j = 0; j < 2; j++) {
            const int id = tid + (j << 8);
            const int row = id >> 2, ch = id & 3;     // 4 x 16B chunks per 32-col row
            const uint32_t so = (uint32_t)(row * 80 + ch * 16) + buf * BUFB;
            cp_async16(sA + so, Ap + (size_t)row * LDP + ao + ch * 8);
            cp_async16(sB + so, Bp + (size_t)row * LDP + bo + ch * 8);
        }
        cp_commit();
    };

    issue(0, 0);
    for (int t = 0; t < NT; t++) {
        if (t + 1 < NT) { issue((t + 1) & 1, t + 1); cp_wait<1>(); }
        else           { cp_wait<0>(); }
        __syncthreads();
        const uint32_t bufo = (t & 1) * BUFB;
        #pragma unroll
        for (int ks = 0; ks < 2; ks++) {
            uint32_t a[2][4], b[4][4];
            #pragma unroll
            for (int i = 0; i < 2; i++)
                ldsm4(a[i], sA + bufo + (warp_m * 32 + i * 16 + arow) * 80 + ks * 32 + akb);
            #pragma unroll
            for (int g = 0; g < 4; g++)
                ldsm4(b[g], sB + bufo + (warp_n * 64 + g * 16 + brow) * 80 + ks * 32 + bkb);
            #pragma unroll
            for (int i = 0; i < 2; i++)
                #pragma unroll
                for (int g = 0; g < 4; g++) {
                    mma16816(c[i][g * 2 + 0], a[i], &b[g][0]);
                    mma16816(c[i][g * 2 + 1], a[i], &b[g][2]);
                }
        }
        __syncthreads();
    }

    // epilogue
    const int gid = lane >> 2, tg = lane & 3;
    #pragma unroll
    for (int i = 0; i < 2; i++) {
        const int row = m0 + warp_m * 32 + i * 16 + gid;
        #pragma unroll
        for (int j = 0; j < 8; j++) {
            const int col = n0 + warp_n * 64 + j * 8 + tg * 2;
            float b0 = 0.f, b1 = 0.f;
            if (bias) { b0 = bias[col]; b1 = bias[col + 1]; }
            *(float2*)&C[(size_t)row * N + col] =
                make_float2(c[i][j][0] + b0, c[i][j][1] + b1);
            *(float2*)&C[(size_t)(row + 8) * N + col] =
                make_float2(c[i][j][2] + b0, c[i][j][3] + b1);
        }
    }
}

// ---------------------------------------------------------------------------
// Rotary (first 64 dims/head) + kv scatter. qkv: [t][12288] = q|k|v (NH,HS).
// ---------------------------------------------------------------------------
__global__ __launch_bounds__(256) void rotary_scatter(
    const float* __restrict__ qkv, const float* __restrict__ cosb,
    const float* __restrict__ sinb, const int* __restrict__ slots,
    float* __restrict__ qout, float* __restrict__ kout, float* __restrict__ vout)
{
    const int idx = blockIdx.x * 256 + threadIdx.x;
    const int t = idx >> 12;
    const int hd = idx & 4095;
    const int d = hd & 127;
    const float* base = qkv + (size_t)t * 12288;
    float qv = base[hd];
    float kv = base[4096 + hd];
    const float vv = base[8192 + hd];
    if (d < 64) {
        const int half = d & 31;
        const float c = cosb[(t << 5) + half];
        const float s = sinb[(t << 5) + half];
        if (d < 32) {
            qv = qv * c - base[hd + 32] * s;
            kv = kv * c - base[4096 + hd + 32] * s;
        } else {
            qv = qv * c + base[hd - 32] * s;
            kv = kv * c + base[4096 + hd - 32] * s;
        }
    }
    qout[idx] = qv;
    const size_t ko = ((size_t)slots[t] << 12) + hd;
    kout[ko] = kv;
    vout[ko] = vv;
}

// ---------------------------------------------------------------------------
// Causal flash attention, fp32. Br=Bc=64, 256 threads. grid (S/64, NH, B).
// ---------------------------------------------------------------------------
__global__ __launch_bounds__(256) void attn_kernel(
    const float* __restrict__ Q, const float* __restrict__ Kc,
    const float* __restrict__ Vc, float* __restrict__ O)
{
    extern __shared__ float smf[];
    float* Qs   = smf;
    float* Ks   = Qs + 64 * 128;
    float* Vs   = Ks + 64 * 129;
    float* Ps   = Vs + 64 * 132;
    float* mrow = Ps + 64 * 66;
    float* lrow = mrow + 64;
    float* arow = lrow + 64;

    const int qi = blockIdx.x, h = blockIdx.y, b = blockIdx.z;
    const int tid = threadIdx.x;
    const int tx = tid & 15, ty = tid >> 4;
    const int q0 = qi << 6;
    const float scale = 0.08838834764831845f;

    #pragma unroll
    for (int i = 0; i < 8; i++) {
        const int f = tid + (i << 8);
        const int r = f >> 5, dq = f & 31;
        const float4 v = *(const float4*)&Q[(size_t)(b * SEQ + q0 + r) * HIDN + h * HSZ + dq * 4];
        *(float4*)&Qs[r * 128 + dq * 4] =
            make_float4(v.x * scale, v.y * scale, v.z * scale, v.w * scale);
    }
    if (tid < 64) { mrow[tid] = -1e30f; lrow[tid] = 0.f; }
    float o[4][8];
    #pragma unroll
    for (int i = 0; i < 4; i++)
        #pragma unroll
        for (int j = 0; j < 8; j++) o[i][j] = 0.f;
    __syncthreads();

    for (int kt = 0; kt <= qi; kt++) {
        #pragma unroll
        for (int i = 0; i < 8; i++) {
            const int f = tid + (i << 8);
            const int r = f >> 5, dq = f & 31;
            const size_t g = (size_t)(b * SEQ + (kt << 6) + r) * HIDN + h * HSZ + dq * 4;
            const float4 kv = *(const float4*)&Kc[g];
            Ks[r * 129 + dq * 4 + 0] = kv.x; Ks[r * 129 + dq * 4 + 1] = kv.y;
            Ks[r * 129 + dq * 4 + 2] = kv.z; Ks[r * 129 + dq * 4 + 3] = kv.w;
            *(float4*)&Vs[r * 132 + dq * 4] = *(const float4*)&Vc[g];
        }
        __syncthreads();

        float s[4][4];
        #pragma unroll
        for (int i = 0; i < 4; i++)
            #pragma unroll
            for (int j = 0; j < 4; j++) s[i][j] = 0.f;
        #pragma unroll 4
        for (int d = 0; d < 128; d++) {
            float qr[4], kr[4];
            #pragma unroll
            for (int i = 0; i < 4; i++) qr[i] = Qs[(ty * 4 + i) * 128 + d];
            #pragma unroll
            for (int j = 0; j < 4; j++) kr[j] = Ks[(tx * 4 + j) * 129 + d];
            #pragma unroll
            for (int i = 0; i < 4; i++)
                #pragma unroll
                for (int j = 0; j < 4; j++)
                    s[i][j] = fmaf(qr[i], kr[j], s[i][j]);
        }
        #pragma unroll
        for (int i = 0; i < 4; i++) {
            const int qr_ = q0 + ty * 4 + i;
            #pragma unroll
            for (int j = 0; j < 4; j++) {
                const int kc = (kt << 6) + tx * 4 + j;
                Ps[(ty * 4 + i) * 66 + tx * 4 + j] = (kc <= qr_) ? s[i][j] : -1e30f;
            }
        }
        __syncthreads();

        if (tid < 64) {
            float mold = mrow[tid];
            float mnew = mold;
            float* pr = &Ps[tid * 66];
            #pragma unroll 8
            for (int cc = 0; cc < 64; cc++) mnew = fmaxf(mnew, pr[cc]);
            const float alpha = __expf(mold - mnew);
            float lsum = 0.f;
            #pragma unroll 8
            for (int cc = 0; cc < 64; cc++) {
                const float p = __expf(pr[cc] - mnew);
                pr[cc] = p; lsum += p;
            }
            lrow[tid] = lrow[tid] * alpha + lsum;
            mrow[tid] = mnew;
            arow[tid] = alpha;
        }
        __syncthreads();

        float al[4];
        #pragma unroll
        for (int i = 0; i < 4; i++) al[i] = arow[ty * 4 + i];
        #pragma unroll
        for (int i = 0; i < 4; i++)
            #pragma unroll
            for (int j = 0; j < 8; j++) o[i][j] *= al[i];
        #pragma unroll 2
        for (int k = 0; k < 64; k++) {
            float p[4];
            #pragma unroll
            for (int i = 0; i < 4; i++) p[i] = Ps[(ty * 4 + i) * 66 + k];
            const float4 v0 = *(const float4*)&Vs[k * 132 + tx * 8];
            const float4 v1 = *(const float4*)&Vs[k * 132 + tx * 8 + 4];
            const float vv[8] = {v0.x, v0.y, v0.z, v0.w, v1.x, v1.y, v1.z, v1.w};
            #pragma unroll
            for (int i = 0; i < 4; i++)
                #pragma unroll
                for (int j = 0; j < 8; j++)
                    o[i][j] = fmaf(p[i], vv[j], o[i][j]);
        }
        __syncthreads();
    }

    #pragma unroll
    for (int i = 0; i < 4; i++) {
        const float inv = 1.f / lrow[ty * 4 + i];
        float* dst = &O[(size_t)(b * SEQ + q0 + ty * 4 + i) * HIDN + h * HSZ + tx * 8];
        *(float4*)dst       = make_float4(o[i][0] * inv, o[i][1] * inv, o[i][2] * inv, o[i][3] * inv);
        *(float4*)(dst + 4) = make_float4(o[i][4] * inv, o[i][5] * inv, o[i][6] * inv, o[i][7] * inv);
    }
}

// ---------------------------------------------------------------------------
extern "C" void kernel_launch(void* const* d_in, const int* in_sizes, int n_in,
                              void* d_out, int out_size)
{
    (void)in_sizes; (void)n_in; (void)out_size;
    const float* hs     = (const float*)d_in[0];
    const float* cosb   = (const float*)d_in[1];
    const float* sinb   = (const float*)d_in[2];
    const float* wqkv   = (const float*)d_in[3];
    const float* bqkv   = (const float*)d_in[4];
    const float* wdense = (const float*)d_in[5];
    const int*   slots  = (const int*)d_in[8];

    float* out = (float*)d_out;
    float* kvk = out + (size_t)TT * HIDN;
    float* kvv = kvk + (size_t)TT * HIDN;

    float *qkv_p, *q_p, *attn_p;
    __nv_bfloat16 *pa, *pbq, *pbd;
    cudaGetSymbolAddress((void**)&qkv_p,  g_qkv);
    cudaGetSymbolAddress((void**)&q_p,    g_q);
    cudaGetSymbolAddress((void**)&attn_p, g_attn);
    cudaGetSymbolAddress((void**)&pa,     g_pa);
    cudaGetSymbolAddress((void**)&pbq,    g_pbq);
    cudaGetSymbolAddress((void**)&pbd,    g_pbd);

    // pack operands (hi/lo bf16 split)
    pack_a<<<(TT * GK) / 256, 256>>>(hs, pa);
    pack_bt<<<dim3(3 * HIDN / 32, GK / 32), dim3(32, 32)>>>(wqkv, pbq, 3 * HIDN);
    pack_bt<<<dim3(HIDN / 32, GK / 32), dim3(32, 32)>>>(wdense, pbd, HIDN);

    // 1. QKV projection on tensor cores (+bias)
    tgemm<<<dim3(3 * HIDN / 128, TT / 128), 256>>>(pa, pbq, bqkv, qkv_p, TT, 3 * HIDN);

    // 2. rotary + kv-cache scatter
    rotary_scatter<<<(TT * HIDN) / 256, 256>>>(qkv_p, cosb, sinb, slots, q_p, kvk, kvv);

    // 3. causal flash attention (fp32 SIMT)
    const size_t asmem = (size_t)(64 * 128 + 64 * 129 + 64 * 132 + 64 * 66 + 192) * sizeof(float);
    cudaFuncSetAttribute(attn_kernel, cudaFuncAttributeMaxDynamicSharedMemorySize, (int)asmem);
    attn_kernel<<<dim3(SEQ / 64, NHEAD, BATCH), 256, asmem>>>(q_p, kvk, kvv, attn_p);

    // 4. dense projection on tensor cores
    pack_a<<<(TT * GK) / 256, 256>>>(attn_p, pa);
    tgemm<<<dim3(HIDN / 128, TT / 128), 256>>>(pa, pbd, nullptr, out, TT, HIDN);
}

// round 5
// speedup vs baseline: 1.8733x; 1.1598x over previous
#include <cuda_runtime.h>
#include <cuda_bf16.h>
#include <math.h>
#include <stdint.h>

// FlashChatglmAttention: B=4 S=1024 HID=4096 NH=32 HS=128 ROT=64
// R5: fused-split bf16 mma.sync GEMM — per k-tile load Ah/Al/Bh/Bl once and
// issue all 3 split products (Ah*Bh + Al*Bh + Ah*Bl) on one accumulator.
// 3-stage cp.async ring, single __syncthreads per k-tile.

#define TT    4096
#define HIDN  4096
#define NHEAD 32
#define HSZ   128
#define SEQ   1024
#define BATCH 4
#define GK    4096
#define LDP   8192      // packed row stride (hi|lo)

// ---------------- scratch (allocation-free) ----------------
__device__ float g_qkv [(size_t)TT * 3 * HIDN];
__device__ float g_q   [(size_t)TT * HIDN];
__device__ float g_attn[(size_t)TT * HIDN];
__device__ __nv_bfloat16 g_pa [(size_t)TT * LDP];
__device__ __nv_bfloat16 g_pbq[(size_t)3 * HIDN * LDP];
__device__ __nv_bfloat16 g_pbd[(size_t)HIDN * LDP];

// ---------------- PTX helpers (baseline ISA only) ----------------
__device__ __forceinline__ uint32_t smem_u32(const void* p) {
    uint32_t a;
    asm("{ .reg .u64 t; cvta.to.shared.u64 t, %1; cvt.u32.u64 %0, t; }" : "=r"(a) : "l"(p));
    return a;
}
__device__ __forceinline__ void cp_async16(uint32_t saddr, const void* gaddr) {
    asm volatile("cp.async.cg.shared.global [%0], [%1], 16;" :: "r"(saddr), "l"(gaddr));
}
__device__ __forceinline__ void cp_commit() { asm volatile("cp.async.commit_group;"); }
template<int N> __device__ __forceinline__ void cp_wait() {
    asm volatile("cp.async.wait_group %0;" :: "n"(N));
}
__device__ __forceinline__ void ldsm4(uint32_t* r, uint32_t addr) {
    asm volatile("ldmatrix.sync.aligned.m8n8.x4.shared.b16 {%0,%1,%2,%3}, [%4];"
                 : "=r"(r[0]), "=r"(r[1]), "=r"(r[2]), "=r"(r[3]) : "r"(addr));
}
__device__ __forceinline__ void mma16816(float* c, const uint32_t* a, const uint32_t* b) {
    asm volatile("mma.sync.aligned.m16n8k16.row.col.f32.bf16.bf16.f32 "
                 "{%0,%1,%2,%3}, {%4,%5,%6,%7}, {%8,%9}, {%0,%1,%2,%3};"
                 : "+f"(c[0]), "+f"(c[1]), "+f"(c[2]), "+f"(c[3])
                 : "r"(a[0]), "r"(a[1]), "r"(a[2]), "r"(a[3]), "r"(b[0]), "r"(b[1]));
}

// ---------------------------------------------------------------------------
// Pack kernels: fp32 -> bf16 hi | lo (residual).
// ---------------------------------------------------------------------------
__global__ __launch_bounds__(256) void pack_a(const float* __restrict__ X,
                                              __nv_bfloat16* __restrict__ Y) {
    const int idx = blockIdx.x * 256 + threadIdx.x;
    const int m = idx >> 12, k = idx & 4095;
    const float x = X[idx];
    const __nv_bfloat16 h = __float2bfloat16(x);
    const float r = x - __bfloat162float(h);
    Y[(size_t)m * LDP + k]      = h;
    Y[(size_t)m * LDP + GK + k] = __float2bfloat16(r);
}

// transpose pack: W[K][N] -> Y[N][hi(K)|lo(K)]
__global__ __launch_bounds__(1024) void pack_bt(const float* __restrict__ W,
                                                __nv_bfloat16* __restrict__ Y, int N) {
    __shared__ float sm[32][33];
    const int n0 = blockIdx.x << 5, k0 = blockIdx.y << 5;
    sm[threadIdx.y][threadIdx.x] = W[(size_t)(k0 + threadIdx.y) * N + n0 + threadIdx.x];
    __syncthreads();
    const float x = sm[threadIdx.x][threadIdx.y];       // W[k0+tx][n0+ty]
    const int n = n0 + threadIdx.y, k = k0 + threadIdx.x;
    const __nv_bfloat16 h = __float2bfloat16(x);
    const float r = x - __bfloat162float(h);
    Y[(size_t)n * LDP + k]      = h;
    Y[(size_t)n * LDP + GK + k] = __float2bfloat16(r);
}

// ---------------------------------------------------------------------------
// Fused-split bf16 mma.sync GEMM.
// A packed [M][2*GK], Bt packed [N][2*GK]. 128x128 CTA tile, BK=32,
// 8 warps (4x2), 32x64 warp tile. Per k-tile: Ah|Al|Bh|Bl in smem,
// 3 MMA combos. 3-stage cp.async ring, 1 sync/iter.
// ---------------------------------------------------------------------------
#define TILEB 10240u               // bytes per operand tile (128 rows * 80B)
#define STAGEB (4u * TILEB)        // Ah|Al|Bh|Bl
#define NSTAGE 3
#define GEMM_SMEM (NSTAGE * STAGEB)   // 122880 B

__global__ __launch_bounds__(256, 1) void tgemm(
    const __nv_bfloat16* __restrict__ A, const __nv_bfloat16* __restrict__ Bt,
    const float* __restrict__ bias, float* __restrict__ C, int M, int N)
{
    extern __shared__ __align__(16) char smraw[];
    const uint32_t sS = smem_u32(smraw);

    const int tid = threadIdx.x;
    const int wid = tid >> 5, lane = tid & 31;
    const int warp_m = wid >> 1, warp_n = wid & 1;

    const int m0 = blockIdx.y << 7, n0 = blockIdx.x << 7;
    const __nv_bfloat16* Ap = A + (size_t)m0 * LDP;
    const __nv_bfloat16* Bp = Bt + (size_t)n0 * LDP;

    // ldmatrix per-lane address components
    const int arow = lane & 15;                       // A: row within m16 tile
    const int akb  = (lane >> 4) * 16;                // A: k-byte offset
    const int brow = ((lane >> 4) << 3) + (lane & 7); // B: row within n16 tile
    const int bkb  = ((lane >> 3) & 1) * 16;          // B: k-byte offset

    float c[2][8][4];
    #pragma unroll
    for (int i = 0; i < 2; i++)
        #pragma unroll
        for (int j = 0; j < 8; j++)
            #pragma unroll
            for (int v = 0; v < 4; v++) c[i][j][v] = 0.f;

    const int NT = GK / 32;   // 128 k-tiles

    // loader: each thread moves 2 x 16B chunks per operand tile
    const int lrow0 = tid >> 2, lch = tid & 3;
    const uint32_t so0 = (uint32_t)(lrow0 * 80 + lch * 16);
    const uint32_t so1 = (uint32_t)((lrow0 + 64) * 80 + lch * 16);
    const __nv_bfloat16* Ag0 = Ap + (size_t)lrow0 * LDP + lch * 8;
    const __nv_bfloat16* Ag1 = Ap + (size_t)(lrow0 + 64) * LDP + lch * 8;
    const __nv_bfloat16* Bg0 = Bp + (size_t)lrow0 * LDP + lch * 8;
    const __nv_bfloat16* Bg1 = Bp + (size_t)(lrow0 + 64) * LDP + lch * 8;

    auto issue = [&](int t) {
        const uint32_t sb = sS + (uint32_t)(t % NSTAGE) * STAGEB;
        const int ko = t * 32;
        cp_async16(sb + so0,                 Ag0 + ko);
        cp_async16(sb + so1,                 Ag1 + ko);
        cp_async16(sb + TILEB + so0,         Ag0 + GK + ko);
        cp_async16(sb + TILEB + so1,         Ag1 + GK + ko);
        cp_async16(sb + 2 * TILEB + so0,     Bg0 + ko);
        cp_async16(sb + 2 * TILEB + so1,     Bg1 + ko);
        cp_async16(sb + 3 * TILEB + so0,     Bg0 + GK + ko);
        cp_async16(sb + 3 * TILEB + so1,     Bg1 + GK + ko);
        cp_commit();
    };

    issue(0); issue(1);
    for (int t = 0; t < NT; t++) {
        cp_wait<1>();
        __syncthreads();
        if (t + 2 < NT) issue(t + 2);
        const uint32_t bufo = sS + (uint32_t)(t % NSTAGE) * STAGEB;
        #pragma unroll
        for (int ks = 0; ks < 2; ks++) {
            uint32_t ah[2][4], al[2][4], bh[4][4], bl[4][4];
            #pragma unroll
            for (int i = 0; i < 2; i++) {
                const uint32_t ra = bufo + (warp_m * 32 + i * 16 + arow) * 80 + ks * 32 + akb;
                ldsm4(ah[i], ra);
                ldsm4(al[i], ra + TILEB);
            }
            #pragma unroll
            for (int g = 0; g < 4; g++) {
                const uint32_t rb = bufo + 2 * TILEB + (warp_n * 64 + g * 16 + brow) * 80 + ks * 32 + bkb;
                ldsm4(bh[g], rb);
                ldsm4(bl[g], rb + TILEB);
            }
            #pragma unroll
            for (int i = 0; i < 2; i++)
                #pragma unroll
                for (int g = 0; g < 4; g++) {
                    mma16816(c[i][g * 2 + 0], ah[i], &bh[g][0]);
                    mma16816(c[i][g * 2 + 1], ah[i], &bh[g][2]);
                    mma16816(c[i][g * 2 + 0], al[i], &bh[g][0]);
                    mma16816(c[i][g * 2 + 1], al[i], &bh[g][2]);
                    mma16816(c[i][g * 2 + 0], ah[i], &bl[g][0]);
                    mma16816(c[i][g * 2 + 1], ah[i], &bl[g][2]);
                }
        }
    }

    // epilogue
    const int gid = lane >> 2, tg = lane & 3;
    #pragma unroll
    for (int i = 0; i < 2; i++) {
        const int row = m0 + warp_m * 32 + i * 16 + gid;
        #pragma unroll
        for (int j = 0; j < 8; j++) {
            const int col = n0 + warp_n * 64 + j * 8 + tg * 2;
            float b0 = 0.f, b1 = 0.f;
            if (bias) { b0 = bias[col]; b1 = bias[col + 1]; }
            *(float2*)&C[(size_t)row * N + col] =
                make_float2(c[i][j][0] + b0, c[i][j][1] + b1);
            *(float2*)&C[(size_t)(row + 8) * N + col] =
                make_float2(c[i][j][2] + b0, c[i][j][3] + b1);
        }
    }
}

// ---------------------------------------------------------------------------
// Rotary (first 64 dims/head) + kv scatter. qkv: [t][12288] = q|k|v (NH,HS).
// ---------------------------------------------------------------------------
__global__ __launch_bounds__(256) void rotary_scatter(
    const float* __restrict__ qkv, const float* __restrict__ cosb,
    const float* __restrict__ sinb, const int* __restrict__ slots,
    float* __restrict__ qout, float* __restrict__ kout, float* __restrict__ vout)
{
    const int idx = blockIdx.x * 256 + threadIdx.x;
    const int t = idx >> 12;
    const int hd = idx & 4095;
    const int d = hd & 127;
    const float* base = qkv + (size_t)t * 12288;
    float qv = base[hd];
    float kv = base[4096 + hd];
    const float vv = base[8192 + hd];
    if (d < 64) {
        const int half = d & 31;
        const float c = cosb[(t << 5) + half];
        const float s = sinb[(t << 5) + half];
        if (d < 32) {
            qv = qv * c - base[hd + 32] * s;
            kv = kv * c - base[4096 + hd + 32] * s;
        } else {
            qv = qv * c + base[hd - 32] * s;
            kv = kv * c + base[4096 + hd - 32] * s;
        }
    }
    qout[idx] = qv;
    const size_t ko = ((size_t)slots[t] << 12) + hd;
    kout[ko] = kv;
    vout[ko] = vv;
}

// ---------------------------------------------------------------------------
// Causal flash attention, fp32. Br=Bc=64, 256 threads. grid (S/64, NH, B).
// ---------------------------------------------------------------------------
__global__ __launch_bounds__(256) void attn_kernel(
    const float* __restrict__ Q, const float* __restrict__ Kc,
    const float* __restrict__ Vc, float* __restrict__ O)
{
    extern __shared__ float smf[];
    float* Qs   = smf;
    float* Ks   = Qs + 64 * 128;
    float* Vs   = Ks + 64 * 129;
    float* Ps   = Vs + 64 * 132;
    float* mrow = Ps + 64 * 66;
    float* lrow = mrow + 64;
    float* arow = lrow + 64;

    const int qi = blockIdx.x, h = blockIdx.y, b = blockIdx.z;
    const int tid = threadIdx.x;
    const int tx = tid & 15, ty = tid >> 4;
    const int q0 = qi << 6;
    const float scale = 0.08838834764831845f;

    #pragma unroll
    for (int i = 0; i < 8; i++) {
        const int f = tid + (i << 8);
        const int r = f >> 5, dq = f & 31;
        const float4 v = *(const float4*)&Q[(size_t)(b * SEQ + q0 + r) * HIDN + h * HSZ + dq * 4];
        *(float4*)&Qs[r * 128 + dq * 4] =
            make_float4(v.x * scale, v.y * scale, v.z * scale, v.w * scale);
    }
    if (tid < 64) { mrow[tid] = -1e30f; lrow[tid] = 0.f; }
    float o[4][8];
    #pragma unroll
    for (int i = 0; i < 4; i++)
        #pragma unroll
        for (int j = 0; j < 8; j++) o[i][j] = 0.f;
    __syncthreads();

    for (int kt = 0; kt <= qi; kt++) {
        #pragma unroll
        for (int i = 0; i < 8; i++) {
            const int f = tid + (i << 8);
            const int r = f >> 5, dq = f & 31;
            const size_t g = (size_t)(b * SEQ + (kt << 6) + r) * HIDN + h * HSZ + dq * 4;
            const float4 kv = *(const float4*)&Kc[g];
            Ks[r * 129 + dq * 4 + 0] = kv.x; Ks[r * 129 + dq * 4 + 1] = kv.y;
            Ks[r * 129 + dq * 4 + 2] = kv.z; Ks[r * 129 + dq * 4 + 3] = kv.w;
            *(float4*)&Vs[r * 132 + dq * 4] = *(const float4*)&Vc[g];
        }
        __syncthreads();

        float s[4][4];
        #pragma unroll
        for (int i = 0; i < 4; i++)
            #pragma unroll
            for (int j = 0; j < 4; j++) s[i][j] = 0.f;
        #pragma unroll 4
        for (int d = 0; d < 128; d++) {
            float qr[4], kr[4];
            #pragma unroll
            for (int i = 0; i < 4; i++) qr[i] = Qs[(ty * 4 + i) * 128 + d];
            #pragma unroll
            for (int j = 0; j < 4; j++) kr[j] = Ks[(tx * 4 + j) * 129 + d];
            #pragma unroll
            for (int i = 0; i < 4; i++)
                #pragma unroll
                for (int j = 0; j < 4; j++)
                    s[i][j] = fmaf(qr[i], kr[j], s[i][j]);
        }
        #pragma unroll
        for (int i = 0; i < 4; i++) {
            const int qr_ = q0 + ty * 4 + i;
            #pragma unroll
            for (int j = 0; j < 4; j++) {
                const int kc = (kt << 6) + tx * 4 + j;
                Ps[(ty * 4 + i) * 66 + tx * 4 + j] = (kc <= qr_) ? s[i][j] : -1e30f;
            }
        }
        __syncthreads();

        if (tid < 64) {
            float mold = mrow[tid];
            float mnew = mold;
            float* pr = &Ps[tid * 66];
            #pragma unroll 8
            for (int cc = 0; cc < 64; cc++) mnew = fmaxf(mnew, pr[cc]);
            const float alpha = __expf(mold - mnew);
            float lsum = 0.f;
            #pragma unroll 8
            for (int cc = 0; cc < 64; cc++) {
                const float p = __expf(pr[cc] - mnew);
                pr[cc] = p; lsum += p;
            }
            lrow[tid] = lrow[tid] * alpha + lsum;
            mrow[tid] = mnew;
            arow[tid] = alpha;
        }
        __syncthreads();

        float al[4];
        #pragma unroll
        for (int i = 0; i < 4; i++) al[i] = arow[ty * 4 + i];
        #pragma unroll
        for (int i = 0; i < 4; i++)
            #pragma unroll
            for (int j = 0; j < 8; j++) o[i][j] *= al[i];
        #pragma unroll 2
        for (int k = 0; k < 64; k++) {
            float p[4];
            #pragma unroll
            for (int i = 0; i < 4; i++) p[i] = Ps[(ty * 4 + i) * 66 + k];
            const float4 v0 = *(const float4*)&Vs[k * 132 + tx * 8];
            const float4 v1 = *(const float4*)&Vs[k * 132 + tx * 8 + 4];
            const float vv[8] = {v0.x, v0.y, v0.z, v0.w, v1.x, v1.y, v1.z, v1.w};
            #pragma unroll
            for (int i = 0; i < 4; i++)
                #pragma unroll
                for (int j = 0; j < 8; j++)
                    o[i][j] = fmaf(p[i], vv[j], o[i][j]);
        }
        __syncthreads();
    }

    #pragma unroll
    for (int i = 0; i < 4; i++) {
        const float inv = 1.f / lrow[ty * 4 + i];
        float* dst = &O[(size_t)(b * SEQ + q0 + ty * 4 + i) * HIDN + h * HSZ + tx * 8];
        *(float4*)dst       = make_float4(o[i][0] * inv, o[i][1] * inv, o[i][2] * inv, o[i][3] * inv);
        *(float4*)(dst + 4) = make_float4(o[i][4] * inv, o[i][5] * inv, o[i][6] * inv, o[i][7] * inv);
    }
}

// ---------------------------------------------------------------------------
extern "C" void kernel_launch(void* const* d_in, const int* in_sizes, int n_in,
                              void* d_out, int out_size)
{
    (void)in_sizes; (void)n_in; (void)out_size;
    const float* hs     = (const float*)d_in[0];
    const float* cosb   = (const float*)d_in[1];
    const float* sinb   = (const float*)d_in[2];
    const float* wqkv   = (const float*)d_in[3];
    const float* bqkv   = (const float*)d_in[4];
    const float* wdense = (const float*)d_in[5];
    const int*   slots  = (const int*)d_in[8];

    float* out = (float*)d_out;
    float* kvk = out + (size_t)TT * HIDN;
    float* kvv = kvk + (size_t)TT * HIDN;

    float *qkv_p, *q_p, *attn_p;
    __nv_bfloat16 *pa, *pbq, *pbd;
    cudaGetSymbolAddress((void**)&qkv_p,  g_qkv);
    cudaGetSymbolAddress((void**)&q_p,    g_q);
    cudaGetSymbolAddress((void**)&attn_p, g_attn);
    cudaGetSymbolAddress((void**)&pa,     g_pa);
    cudaGetSymbolAddress((void**)&pbq,    g_pbq);
    cudaGetSymbolAddress((void**)&pbd,    g_pbd);

    cudaFuncSetAttribute(tgemm, cudaFuncAttributeMaxDynamicSharedMemorySize, GEMM_SMEM);

    // pack operands (hi/lo bf16 split)
    pack_a<<<(TT * GK) / 256, 256>>>(hs, pa);
    pack_bt<<<dim3(3 * HIDN / 32, GK / 32), dim3(32, 32)>>>(wqkv, pbq, 3 * HIDN);
    pack_bt<<<dim3(HIDN / 32, GK / 32), dim3(32, 32)>>>(wdense, pbd, HIDN);

    // 1. QKV projection on tensor cores (+bias)
    tgemm<<<dim3(3 * HIDN / 128, TT / 128), 256, GEMM_SMEM>>>(pa, pbq, bqkv, qkv_p, TT, 3 * HIDN);

    // 2. rotary + kv-cache scatter
    rotary_scatter<<<(TT * HIDN) / 256, 256>>>(qkv_p, cosb, sinb, slots, q_p, kvk, kvv);

    // 3. causal flash attention (fp32 SIMT)
    const size_t asmem = (size_t)(64 * 128 + 64 * 129 + 64 * 132 + 64 * 66 + 192) * sizeof(float);
    cudaFuncSetAttribute(attn_kernel, cudaFuncAttributeMaxDynamicSharedMemorySize, (int)asmem);
    attn_kernel<<<dim3(SEQ / 64, NHEAD, BATCH), 256, asmem>>>(q_p, kvk, kvv, attn_p);

    // 4. dense projection on tensor cores
    pack_a<<<(TT * GK) / 256, 256>>>(attn_p, pa);
    tgemm<<<dim3(HIDN / 128, TT / 128), 256, GEMM_SMEM>>>(pa, pbd, nullptr, out, TT, HIDN);
}